// round 5
// baseline (speedup 1.0000x reference)
#include <cuda_runtime.h>
#include <cuda_bf16.h>

#define NG   768
#define H    128
#define PAD  132   // smem row stride in floats; 132*4=528B, 16B-aligned, bank-staggered

// Scratch: columns [0:128)=Ai, [128:256)=Bjb (=Bj+b1), [256:384)=Q (=Wb·x_j rows)
__device__ float g_pre[NG * 384];

// ---------------------------------------------------------------------------
// Kernel 1: precompute the three per-gene projections as one 768x384x128 GEMM.
// All three weight blocks are accessed as contiguous 128-float rows:
//   kk<128   : W1[kk][0:128]
//   kk<256   : W1[kk-128][128:256]  (+ b1[kk-128] in epilogue)
//   kk<384   : Wb[kk-256][0:128]
// ---------------------------------------------------------------------------
__global__ __launch_bounds__(256) void prep_kernel(
    const float* __restrict__ X, const float* __restrict__ W1,
    const float* __restrict__ b1, const float* __restrict__ Wb)
{
    extern __shared__ float sm[];
    float* Xs = sm;              // 64 rows x PAD
    float* Ws = sm + 64 * PAD;   // 64 rows x PAD

    const int i0 = blockIdx.y * 64;
    const int c0 = blockIdx.x * 64;
    const int tid = threadIdx.x;

    // Load X tile (64x128) and weight tile (64x128), float4-coalesced.
    for (int q = tid; q < 2048; q += 256) {
        int r = q >> 5, mq = q & 31;
        *(float4*)(Xs + r * PAD + mq * 4) =
            *(const float4*)(X + (i0 + r) * H + mq * 4);
    }
    for (int q = tid; q < 2048; q += 256) {
        int r = q >> 5, mq = q & 31;
        int kk = c0 + r;
        const float* rp;
        if (kk < 128)      rp = W1 + kk * 256;
        else if (kk < 256) rp = W1 + (kk - 128) * 256 + 128;
        else               rp = Wb + (kk - 256) * 128;
        *(float4*)(Ws + r * PAD + mq * 4) = *(const float4*)(rp + mq * 4);
    }
    __syncthreads();

    const int tx = tid & 15, ty = tid >> 4;
    const int rl = ty * 4, cl = tx * 4;

    float acc[16];
#pragma unroll
    for (int p = 0; p < 16; p++) acc[p] = 0.f;

#pragma unroll 1
    for (int m0 = 0; m0 < 128; m0 += 4) {
        float4 xr[4], wc[4];
#pragma unroll
        for (int r = 0; r < 4; r++) xr[r] = *(float4*)(Xs + (rl + r) * PAD + m0);
#pragma unroll
        for (int c = 0; c < 4; c++) wc[c] = *(float4*)(Ws + (cl + c) * PAD + m0);
#pragma unroll
        for (int r = 0; r < 4; r++)
#pragma unroll
            for (int c = 0; c < 4; c++) {
                acc[r * 4 + c] += xr[r].x * wc[c].x;
                acc[r * 4 + c] += xr[r].y * wc[c].y;
                acc[r * 4 + c] += xr[r].z * wc[c].z;
                acc[r * 4 + c] += xr[r].w * wc[c].w;
            }
    }

#pragma unroll
    for (int r = 0; r < 4; r++)
#pragma unroll
        for (int c = 0; c < 4; c++) {
            int kk = c0 + cl + c;
            float v = acc[r * 4 + c];
            if (kk >= 128 && kk < 256) v += b1[kk - 128];
            g_pre[(i0 + rl + r) * 384 + kk] = v;
        }
}

// ---------------------------------------------------------------------------
// Kernel 2: fused pairwise MLP + argmax + bilinear sign-combine.
// 64x64 output tile / block, 4x4 micro-tile / thread (256 threads).
// Per (i,j,k): t = relu(Ai[i,k]+Bjb[j,k]); l0..l2 += t*W2[c,k]; af += X[i,k]*Q[j,k]
// ---------------------------------------------------------------------------
__global__ __launch_bounds__(256) void pair_kernel(
    const float* __restrict__ X, const float* __restrict__ W2,
    const float* __restrict__ b2, const float* __restrict__ bb,
    float* __restrict__ out)
{
    extern __shared__ float sm[];
    float* As  = sm;                 // Ai  rows (i-side)
    float* Xi  = sm + 64 * PAD;      // X   rows (i-side)
    float* Bs  = sm + 2 * 64 * PAD;  // Bjb rows (j-side)
    float* Qs  = sm + 3 * 64 * PAD;  // Q   rows (j-side)
    float* w2s = sm + 4 * 64 * PAD;  // 3 x PAD

    const int i0 = blockIdx.y * 64;
    const int j0 = blockIdx.x * 64;
    const int tid = threadIdx.x;

    for (int q = tid; q < 2048; q += 256) {
        int r = q >> 5, mq = q & 31;
        *(float4*)(As + r * PAD + mq * 4) = *(const float4*)(g_pre + (i0 + r) * 384 + mq * 4);
        *(float4*)(Xi + r * PAD + mq * 4) = *(const float4*)(X + (i0 + r) * H + mq * 4);
        *(float4*)(Bs + r * PAD + mq * 4) = *(const float4*)(g_pre + (j0 + r) * 384 + 128 + mq * 4);
        *(float4*)(Qs + r * PAD + mq * 4) = *(const float4*)(g_pre + (j0 + r) * 384 + 256 + mq * 4);
    }
    // W2 has 384 elements but only 256 threads: grid-stride (this was the R3 bug).
    for (int q = tid; q < 384; q += 256)
        w2s[(q >> 7) * PAD + (q & 127)] = W2[q];
    __syncthreads();

    const float b20 = b2[0], b21 = b2[1], b22 = b2[2], bb0 = bb[0];
    const int tx = tid & 15, ty = tid >> 4;
    const int il = ty * 4, jl = tx * 4;

    float l0[16], l1[16], l2[16], af[16];
#pragma unroll
    for (int p = 0; p < 16; p++) { l0[p] = b20; l1[p] = b21; l2[p] = b22; af[p] = bb0; }

#pragma unroll 1
    for (int k0 = 0; k0 < 128; k0 += 4) {
        float4 a[4], x[4], b[4], q[4];
#pragma unroll
        for (int r = 0; r < 4; r++) {
            a[r] = *(float4*)(As + (il + r) * PAD + k0);
            x[r] = *(float4*)(Xi + (il + r) * PAD + k0);
        }
#pragma unroll
        for (int c = 0; c < 4; c++) {
            b[c] = *(float4*)(Bs + (jl + c) * PAD + k0);
            q[c] = *(float4*)(Qs + (jl + c) * PAD + k0);
        }
        const float4 w0  = *(float4*)(w2s + k0);
        const float4 w1  = *(float4*)(w2s + PAD + k0);
        const float4 w2v = *(float4*)(w2s + 2 * PAD + k0);

#pragma unroll
        for (int r = 0; r < 4; r++)
#pragma unroll
            for (int c = 0; c < 4; c++) {
                const int p = r * 4 + c;
                float t;
                t = fmaxf(a[r].x + b[c].x, 0.f);
                l0[p] += t * w0.x; l1[p] += t * w1.x; l2[p] += t * w2v.x;
                af[p] += x[r].x * q[c].x;
                t = fmaxf(a[r].y + b[c].y, 0.f);
                l0[p] += t * w0.y; l1[p] += t * w1.y; l2[p] += t * w2v.y;
                af[p] += x[r].y * q[c].y;
                t = fmaxf(a[r].z + b[c].z, 0.f);
                l0[p] += t * w0.z; l1[p] += t * w1.z; l2[p] += t * w2v.z;
                af[p] += x[r].z * q[c].z;
                t = fmaxf(a[r].w + b[c].w, 0.f);
                l0[p] += t * w0.w; l1[p] += t * w1.w; l2[p] += t * w2v.w;
                af[p] += x[r].w * q[c].w;
            }
    }

#pragma unroll
    for (int r = 0; r < 4; r++)
#pragma unroll
        for (int c = 0; c < 4; c++) {
            const int p = r * 4 + c;
            const int i = i0 + il + r, j = j0 + jl + c;
            // first-max argmax: cls0 iff l0>=l1 && l0>=l2; else cls1 iff l1>=l2; else cls2
            const bool is0 = (l0[p] >= l1[p]) && (l0[p] >= l2[p]);
            const bool is2 = !is0 && (l2[p] > l1[p]);
            float v = is0 ? af[p] : (is2 ? -af[p] : 0.f);
            if (i == j) v = 0.f;
            out[i * NG + j] = v;
        }
}

extern "C" void kernel_launch(void* const* d_in, const int* in_sizes, int n_in,
                              void* d_out, int out_size)
{
    const float* X  = (const float*)d_in[0];  // [768,128]
    const float* W1 = (const float*)d_in[1];  // [128,256]
    const float* b1 = (const float*)d_in[2];  // [128]
    const float* W2 = (const float*)d_in[3];  // [3,128]
    const float* b2 = (const float*)d_in[4];  // [3]
    const float* Wb = (const float*)d_in[5];  // [1,128,128]
    const float* bb = (const float*)d_in[6];  // [1]
    float* out = (float*)d_out;

    const int smemA = 2 * 64 * PAD * (int)sizeof(float);                 // 67584 B
    const int smemB = (4 * 64 * PAD + 3 * PAD) * (int)sizeof(float);     // 136752 B
    cudaFuncSetAttribute(prep_kernel, cudaFuncAttributeMaxDynamicSharedMemorySize, smemA);
    cudaFuncSetAttribute(pair_kernel, cudaFuncAttributeMaxDynamicSharedMemorySize, smemB);

    prep_kernel<<<dim3(6, 12), 256, smemA>>>(X, W1, b1, Wb);
    pair_kernel<<<dim3(12, 12), 256, smemB>>>(X, W2, b2, bb, out);
}

// round 7
// speedup vs baseline: 1.3239x; 1.3239x over previous
#include <cuda_runtime.h>
#include <cuda_bf16.h>

#define NG   768
#define H    128
#define PAD  132   // smem row stride in floats; 16B-aligned

// Scratch: columns [0:128)=Ai, [128:256)=Bjb (=Bj+b1), [256:384)=Q (=Wb·x_j rows)
__device__ float g_pre[NG * 384];

// ------------------------- packed f32x2 helpers ----------------------------
__device__ __forceinline__ unsigned long long pk(float lo, float hi) {
    unsigned long long r;
    asm("mov.b64 %0, {%1, %2};" : "=l"(r) : "f"(lo), "f"(hi));
    return r;
}
__device__ __forceinline__ void upk(unsigned long long v, float& lo, float& hi) {
    asm("mov.b64 {%0, %1}, %2;" : "=f"(lo), "=f"(hi) : "l"(v));
}
__device__ __forceinline__ unsigned long long addx2(unsigned long long a, unsigned long long b) {
    unsigned long long r;
    asm("add.rn.f32x2 %0, %1, %2;" : "=l"(r) : "l"(a), "l"(b));
    return r;
}
__device__ __forceinline__ unsigned long long fmax2(unsigned long long a, unsigned long long b,
                                                    unsigned long long c) {
    unsigned long long r;
    asm("fma.rn.f32x2 %0, %1, %2, %3;" : "=l"(r) : "l"(a), "l"(b), "l"(c));
    return r;
}
__device__ __forceinline__ unsigned long long relux2(unsigned long long s) {
    float lo, hi;
    upk(s, lo, hi);
    lo = fmaxf(lo, 0.f);   // FMNMX: alu pipe, overlaps fma pipe
    hi = fmaxf(hi, 0.f);
    return pk(lo, hi);
}

// ---------------------------------------------------------------------------
// Kernel 1: precompute the three per-gene projections as one 768x384x128 GEMM.
// ---------------------------------------------------------------------------
__global__ __launch_bounds__(256) void prep_kernel(
    const float* __restrict__ X, const float* __restrict__ W1,
    const float* __restrict__ b1, const float* __restrict__ Wb)
{
    extern __shared__ float sm[];
    float* Xs = sm;              // 64 rows x PAD
    float* Ws = sm + 64 * PAD;   // 64 rows x PAD

    const int i0 = blockIdx.y * 64;
    const int c0 = blockIdx.x * 64;
    const int tid = threadIdx.x;

    for (int q = tid; q < 2048; q += 256) {
        int r = q >> 5, mq = q & 31;
        *(float4*)(Xs + r * PAD + mq * 4) =
            *(const float4*)(X + (i0 + r) * H + mq * 4);
    }
    for (int q = tid; q < 2048; q += 256) {
        int r = q >> 5, mq = q & 31;
        int kk = c0 + r;
        const float* rp;
        if (kk < 128)      rp = W1 + kk * 256;
        else if (kk < 256) rp = W1 + (kk - 128) * 256 + 128;
        else               rp = Wb + (kk - 256) * 128;
        *(float4*)(Ws + r * PAD + mq * 4) = *(const float4*)(rp + mq * 4);
    }
    __syncthreads();

    const int tx = tid & 15, ty = tid >> 4;
    const int rl = ty * 4, cl = tx * 4;

    float acc[16];
#pragma unroll
    for (int p = 0; p < 16; p++) acc[p] = 0.f;

#pragma unroll 1
    for (int m0 = 0; m0 < 128; m0 += 4) {
        float4 xr[4], wc[4];
#pragma unroll
        for (int r = 0; r < 4; r++) xr[r] = *(float4*)(Xs + (rl + r) * PAD + m0);
#pragma unroll
        for (int c = 0; c < 4; c++) wc[c] = *(float4*)(Ws + (cl + c) * PAD + m0);
#pragma unroll
        for (int r = 0; r < 4; r++)
#pragma unroll
            for (int c = 0; c < 4; c++) {
                acc[r * 4 + c] += xr[r].x * wc[c].x;
                acc[r * 4 + c] += xr[r].y * wc[c].y;
                acc[r * 4 + c] += xr[r].z * wc[c].z;
                acc[r * 4 + c] += xr[r].w * wc[c].w;
            }
    }

#pragma unroll
    for (int r = 0; r < 4; r++)
#pragma unroll
        for (int c = 0; c < 4; c++) {
            int kk = c0 + cl + c;
            float v = acc[r * 4 + c];
            if (kk >= 128 && kk < 256) v += b1[kk - 128];
            g_pre[(i0 + rl + r) * 384 + kk] = v;
        }
}

// ---------------------------------------------------------------------------
// Kernel 2: fused pairwise MLP + argmax + bilinear sign-combine.
// 64x64 tile / block, 512 threads, 4x2 micro-tile, packed f32x2 along k.
// Logit differences: u = l0-l1 (weights w0-w1), w = l1-l2 (weights w1-w2).
// ---------------------------------------------------------------------------
__global__ __launch_bounds__(512) void pair_kernel(
    const float* __restrict__ X, const float* __restrict__ W2,
    const float* __restrict__ b2, const float* __restrict__ bb,
    float* __restrict__ out)
{
    extern __shared__ float sm[];
    float* As  = sm;                 // Ai  rows (i-side)
    float* Xi  = sm + 64 * PAD;      // X   rows (i-side)
    float* Bs  = sm + 2 * 64 * PAD;  // Bjb rows (j-side)
    float* Qs  = sm + 3 * 64 * PAD;  // Q   rows (j-side)
    float* wus = sm + 4 * 64 * PAD;        // W2[0]-W2[1], 128 floats
    float* wvs = sm + 4 * 64 * PAD + PAD;  // W2[1]-W2[2], 128 floats

    const int i0 = blockIdx.y * 64;
    const int j0 = blockIdx.x * 64;
    const int tid = threadIdx.x;

    for (int q = tid; q < 2048; q += 512) {
        int r = q >> 5, mq = q & 31;
        *(float4*)(As + r * PAD + mq * 4) = *(const float4*)(g_pre + (i0 + r) * 384 + mq * 4);
        *(float4*)(Xi + r * PAD + mq * 4) = *(const float4*)(X + (i0 + r) * H + mq * 4);
        *(float4*)(Bs + r * PAD + mq * 4) = *(const float4*)(g_pre + (j0 + r) * 384 + 128 + mq * 4);
        *(float4*)(Qs + r * PAD + mq * 4) = *(const float4*)(g_pre + (j0 + r) * 384 + 256 + mq * 4);
    }
    if (tid < 128) {
        wus[tid] = W2[tid]       - W2[128 + tid];
        wvs[tid] = W2[128 + tid] - W2[256 + tid];
    }
    __syncthreads();

    const float u0 = b2[0] - b2[1];
    const float w0 = b2[1] - b2[2];
    const float bb0 = bb[0];

    const int tx = tid & 31, ty = tid >> 5;   // 32 x 16 thread grid
    const int il = ty * 4, jl = tx * 2;

    unsigned long long u[8], w[8], af[8];
#pragma unroll
    for (int p = 0; p < 8; p++) {
        u[p]  = pk(u0, 0.f);
        w[p]  = pk(w0, 0.f);
        af[p] = pk(bb0, 0.f);
    }

#pragma unroll 1
    for (int k0 = 0; k0 < 128; k0 += 4) {
        float4 a4[4], x4[4], b4[2], q4[2];
#pragma unroll
        for (int r = 0; r < 4; r++) {
            a4[r] = *(float4*)(As + (il + r) * PAD + k0);
            x4[r] = *(float4*)(Xi + (il + r) * PAD + k0);
        }
#pragma unroll
        for (int c = 0; c < 2; c++) {
            b4[c] = *(float4*)(Bs + (jl + c) * PAD + k0);
            q4[c] = *(float4*)(Qs + (jl + c) * PAD + k0);
        }
        const float4 wu4 = *(float4*)(wus + k0);
        const float4 wv4 = *(float4*)(wvs + k0);

#pragma unroll
        for (int h = 0; h < 2; h++) {
            const unsigned long long wu2 = h ? pk(wu4.z, wu4.w) : pk(wu4.x, wu4.y);
            const unsigned long long wv2 = h ? pk(wv4.z, wv4.w) : pk(wv4.x, wv4.y);
            unsigned long long au[4], xu[4], bu[2], qu[2];
#pragma unroll
            for (int r = 0; r < 4; r++) {
                au[r] = h ? pk(a4[r].z, a4[r].w) : pk(a4[r].x, a4[r].y);
                xu[r] = h ? pk(x4[r].z, x4[r].w) : pk(x4[r].x, x4[r].y);
            }
#pragma unroll
            for (int c = 0; c < 2; c++) {
                bu[c] = h ? pk(b4[c].z, b4[c].w) : pk(b4[c].x, b4[c].y);
                qu[c] = h ? pk(q4[c].z, q4[c].w) : pk(q4[c].x, q4[c].y);
            }
#pragma unroll
            for (int r = 0; r < 4; r++)
#pragma unroll
                for (int c = 0; c < 2; c++) {
                    const int p = r * 2 + c;
                    unsigned long long t = relux2(addx2(au[r], bu[c]));
                    u[p]  = fmax2(t, wu2, u[p]);
                    w[p]  = fmax2(t, wv2, w[p]);
                    af[p] = fmax2(xu[r], qu[c], af[p]);
                }
        }
    }

#pragma unroll
    for (int r = 0; r < 4; r++) {
        const int i = i0 + il + r;
        float2 vout;
#pragma unroll
        for (int c = 0; c < 2; c++) {
            const int p = r * 2 + c;
            const int j = j0 + jl + c;
            float lo, hi;
            upk(u[p], lo, hi);  const float us = lo + hi;
            upk(w[p], lo, hi);  const float ws = lo + hi;
            upk(af[p], lo, hi); const float as = lo + hi;
            // first-max argmax on differences:
            // is0: l0>=l1 (u>=0) && l0>=l2 (u+w>=0); is2: !is0 && l2>l1 (w<0)
            const bool is0 = (us >= 0.f) && (us + ws >= 0.f);
            const bool is2 = !is0 && (ws < 0.f);
            float v = is0 ? as : (is2 ? -as : 0.f);
            if (i == j) v = 0.f;
            if (c == 0) vout.x = v; else vout.y = v;
        }
        *(float2*)(out + i * NG + j0 + jl) = vout;
    }
}

extern "C" void kernel_launch(void* const* d_in, const int* in_sizes, int n_in,
                              void* d_out, int out_size)
{
    const float* X  = (const float*)d_in[0];  // [768,128]
    const float* W1 = (const float*)d_in[1];  // [128,256]
    const float* b1 = (const float*)d_in[2];  // [128]
    const float* W2 = (const float*)d_in[3];  // [3,128]
    const float* b2 = (const float*)d_in[4];  // [3]
    const float* Wb = (const float*)d_in[5];  // [1,128,128]
    const float* bb = (const float*)d_in[6];  // [1]
    float* out = (float*)d_out;

    const int smemA = 2 * 64 * PAD * (int)sizeof(float);               // 67584 B
    const int smemB = (4 * 64 * PAD + 2 * PAD) * (int)sizeof(float);   // 136224 B
    cudaFuncSetAttribute(prep_kernel, cudaFuncAttributeMaxDynamicSharedMemorySize, smemA);
    cudaFuncSetAttribute(pair_kernel, cudaFuncAttributeMaxDynamicSharedMemorySize, smemB);

    prep_kernel<<<dim3(6, 12), 256, smemA>>>(X, W1, b1, Wb);
    pair_kernel<<<dim3(12, 12), 512, smemB>>>(X, W2, b2, bb, out);
}

// round 8
// speedup vs baseline: 1.7017x; 1.2854x over previous
#include <cuda_runtime.h>
#include <cuda_bf16.h>

#define NG   768
#define H    128
#define PAD  132   // smem row stride in floats; 16B-aligned; PAD%32==4 -> conflict-free col access

typedef unsigned long long u64;

// Scratch: columns [0:128)=Ai, [128:256)=Bjb (=Bj+b1), [256:384)=Q (=Wb·x_j rows)
__device__ float g_pre[NG * 384];

// ------------------------- packed f32x2 helpers ----------------------------
// Pack/unpack via union: pure register-pair typing, no MOV instructions.
union F2U { u64 u; float2 f; };

__device__ __forceinline__ u64 pk2(float lo, float hi) {
    F2U t; t.f = make_float2(lo, hi); return t.u;
}
__device__ __forceinline__ float2 upk2(u64 v) {
    F2U t; t.u = v; return t.f;
}
__device__ __forceinline__ u64 addx2(u64 a, u64 b) {
    u64 r;
    asm("add.rn.f32x2 %0, %1, %2;" : "=l"(r) : "l"(a), "l"(b));
    return r;
}
__device__ __forceinline__ u64 fmax2(u64 a, u64 b, u64 c) {
    u64 r;
    asm("fma.rn.f32x2 %0, %1, %2, %3;" : "=l"(r) : "l"(a), "l"(b), "l"(c));
    return r;
}
__device__ __forceinline__ u64 relux2(u64 s) {
    F2U t; t.u = s;
    t.f.x = fmaxf(t.f.x, 0.f);   // FMNMX on alu pipe, overlaps fma pipe
    t.f.y = fmaxf(t.f.y, 0.f);
    return t.u;
}

// ---------------------------------------------------------------------------
// Kernel 1: per-gene projections as one 768x384x128 GEMM (packed f32x2).
// Output column kk: kk<128 -> Ai (W1 left), kk<256 -> Bjb (W1 right + b1),
// kk<384 -> Q (Wb rows).
// 64x64 tile, 512 threads, 4x2 micro-tile; thread covers cols {tx, tx+32}.
// ---------------------------------------------------------------------------
__global__ __launch_bounds__(512) void prep_kernel(
    const float* __restrict__ X, const float* __restrict__ W1,
    const float* __restrict__ b1, const float* __restrict__ Wb)
{
    extern __shared__ float sm[];
    float* Xs = sm;              // 64 rows x PAD
    float* Ws = sm + 64 * PAD;   // 64 rows x PAD

    const int i0 = blockIdx.y * 64;
    const int c0 = blockIdx.x * 64;
    const int tid = threadIdx.x;

    for (int q = tid; q < 2048; q += 512) {
        int r = q >> 5, mq = q & 31;
        *(float4*)(Xs + r * PAD + mq * 4) =
            *(const float4*)(X + (i0 + r) * H + mq * 4);
    }
    for (int q = tid; q < 2048; q += 512) {
        int r = q >> 5, mq = q & 31;
        int kk = c0 + r;
        const float* rp;
        if (kk < 128)      rp = W1 + kk * 256;
        else if (kk < 256) rp = W1 + (kk - 128) * 256 + 128;
        else               rp = Wb + (kk - 256) * 128;
        *(float4*)(Ws + r * PAD + mq * 4) = *(const float4*)(rp + mq * 4);
    }
    __syncthreads();

    const int tx = tid & 31, ty = tid >> 5;
    const int rl = ty * 4;                    // 4 output rows
    // columns {tx, tx+32}: per-lane stride PAD (mod 32 == 4) -> conflict-free

    u64 acc[8];
#pragma unroll
    for (int p = 0; p < 8; p++) acc[p] = 0ull;

#pragma unroll 1
    for (int m0 = 0; m0 < 128; m0 += 4) {
        ulonglong2 xr[4], wc[2];
#pragma unroll
        for (int r = 0; r < 4; r++)
            xr[r] = *(const ulonglong2*)(Xs + (rl + r) * PAD + m0);
        wc[0] = *(const ulonglong2*)(Ws + tx * PAD + m0);
        wc[1] = *(const ulonglong2*)(Ws + (tx + 32) * PAD + m0);

#pragma unroll
        for (int h = 0; h < 2; h++) {
#pragma unroll
            for (int r = 0; r < 4; r++) {
                const u64 xh = h ? xr[r].y : xr[r].x;
#pragma unroll
                for (int c = 0; c < 2; c++) {
                    const u64 wh = h ? wc[c].y : wc[c].x;
                    acc[r * 2 + c] = fmax2(xh, wh, acc[r * 2 + c]);
                }
            }
        }
    }

#pragma unroll
    for (int r = 0; r < 4; r++)
#pragma unroll
        for (int c = 0; c < 2; c++) {
            const int kk = c0 + tx + c * 32;
            float2 s = upk2(acc[r * 2 + c]);
            float v = s.x + s.y;
            if (kk >= 128 && kk < 256) v += b1[kk - 128];
            g_pre[(i0 + rl + r) * 384 + kk] = v;
        }
}

// ---------------------------------------------------------------------------
// Kernel 2: fused pairwise MLP + argmax + bilinear sign-combine.
// 64x64 tile, 512 threads, 4x2 micro-tile (rows il..il+3, cols {tx, tx+32}),
// packed f32x2 along k. Logit diffs: u = l0-l1, w = l1-l2.
// ---------------------------------------------------------------------------
__global__ __launch_bounds__(512) void pair_kernel(
    const float* __restrict__ X, const float* __restrict__ W2,
    const float* __restrict__ b2, const float* __restrict__ bb,
    float* __restrict__ out)
{
    extern __shared__ float sm[];
    float* As  = sm;                 // Ai  rows (i-side)
    float* Xi  = sm + 64 * PAD;      // X   rows (i-side)
    float* Bs  = sm + 2 * 64 * PAD;  // Bjb rows (j-side)
    float* Qs  = sm + 3 * 64 * PAD;  // Q   rows (j-side)
    float* wus = sm + 4 * 64 * PAD;        // W2[0]-W2[1], 128 floats
    float* wvs = sm + 4 * 64 * PAD + PAD;  // W2[1]-W2[2], 128 floats

    const int i0 = blockIdx.y * 64;
    const int j0 = blockIdx.x * 64;
    const int tid = threadIdx.x;

    for (int q = tid; q < 2048; q += 512) {
        int r = q >> 5, mq = q & 31;
        *(float4*)(As + r * PAD + mq * 4) = *(const float4*)(g_pre + (i0 + r) * 384 + mq * 4);
        *(float4*)(Xi + r * PAD + mq * 4) = *(const float4*)(X + (i0 + r) * H + mq * 4);
        *(float4*)(Bs + r * PAD + mq * 4) = *(const float4*)(g_pre + (j0 + r) * 384 + 128 + mq * 4);
        *(float4*)(Qs + r * PAD + mq * 4) = *(const float4*)(g_pre + (j0 + r) * 384 + 256 + mq * 4);
    }
    if (tid < 128) {
        wus[tid] = W2[tid]       - W2[128 + tid];
        wvs[tid] = W2[128 + tid] - W2[256 + tid];
    }
    __syncthreads();

    const float u0  = b2[0] - b2[1];
    const float w0  = b2[1] - b2[2];
    const float bb0 = bb[0];

    const int tx = tid & 31, ty = tid >> 5;
    const int il = ty * 4;   // cols {tx, tx+32}: stride PAD per lane -> conflict-free

    u64 u[8], w[8], af[8];
#pragma unroll
    for (int p = 0; p < 8; p++) {
        u[p]  = pk2(u0, 0.f);
        w[p]  = pk2(w0, 0.f);
        af[p] = pk2(bb0, 0.f);
    }

#pragma unroll 1
    for (int k0 = 0; k0 < 128; k0 += 4) {
        ulonglong2 a2[4], x2[4], bv[2], qv[2];
#pragma unroll
        for (int r = 0; r < 4; r++) {
            a2[r] = *(const ulonglong2*)(As + (il + r) * PAD + k0);
            x2[r] = *(const ulonglong2*)(Xi + (il + r) * PAD + k0);
        }
        bv[0] = *(const ulonglong2*)(Bs + tx * PAD + k0);
        bv[1] = *(const ulonglong2*)(Bs + (tx + 32) * PAD + k0);
        qv[0] = *(const ulonglong2*)(Qs + tx * PAD + k0);
        qv[1] = *(const ulonglong2*)(Qs + (tx + 32) * PAD + k0);
        const ulonglong2 wu2 = *(const ulonglong2*)(wus + k0);
        const ulonglong2 wv2 = *(const ulonglong2*)(wvs + k0);

#pragma unroll
        for (int h = 0; h < 2; h++) {
            const u64 wuh = h ? wu2.y : wu2.x;
            const u64 wvh = h ? wv2.y : wv2.x;
#pragma unroll
            for (int r = 0; r < 4; r++) {
                const u64 ah = h ? a2[r].y : a2[r].x;
                const u64 xh = h ? x2[r].y : x2[r].x;
#pragma unroll
                for (int c = 0; c < 2; c++) {
                    const int p = r * 2 + c;
                    const u64 bh = h ? bv[c].y : bv[c].x;
                    const u64 qh = h ? qv[c].y : qv[c].x;
                    const u64 t = relux2(addx2(ah, bh));
                    u[p]  = fmax2(t, wuh, u[p]);
                    w[p]  = fmax2(t, wvh, w[p]);
                    af[p] = fmax2(xh, qh, af[p]);
                }
            }
        }
    }

#pragma unroll
    for (int r = 0; r < 4; r++) {
        const int i = i0 + il + r;
#pragma unroll
        for (int c = 0; c < 2; c++) {
            const int p = r * 2 + c;
            const int j = j0 + tx + c * 32;
            float2 s;
            s = upk2(u[p]);  const float us = s.x + s.y;
            s = upk2(w[p]);  const float ws = s.x + s.y;
            s = upk2(af[p]); const float as = s.x + s.y;
            // first-max argmax on differences:
            // is0: l0>=l1 (u>=0) && l0>=l2 (u+w>=0); is2: !is0 && l2>l1 (w<0)
            const bool is0 = (us >= 0.f) && (us + ws >= 0.f);
            const bool is2 = !is0 && (ws < 0.f);
            float v = is0 ? as : (is2 ? -as : 0.f);
            if (i == j) v = 0.f;
            out[i * NG + j] = v;
        }
    }
}

extern "C" void kernel_launch(void* const* d_in, const int* in_sizes, int n_in,
                              void* d_out, int out_size)
{
    const float* X  = (const float*)d_in[0];  // [768,128]
    const float* W1 = (const float*)d_in[1];  // [128,256]
    const float* b1 = (const float*)d_in[2];  // [128]
    const float* W2 = (const float*)d_in[3];  // [3,128]
    const float* b2 = (const float*)d_in[4];  // [3]
    const float* Wb = (const float*)d_in[5];  // [1,128,128]
    const float* bb = (const float*)d_in[6];  // [1]
    float* out = (float*)d_out;

    const int smemA = 2 * 64 * PAD * (int)sizeof(float);               // 67584 B
    const int smemB = (4 * 64 * PAD + 2 * PAD) * (int)sizeof(float);   // 136224 B
    cudaFuncSetAttribute(prep_kernel, cudaFuncAttributeMaxDynamicSharedMemorySize, smemA);
    cudaFuncSetAttribute(pair_kernel, cudaFuncAttributeMaxDynamicSharedMemorySize, smemB);

    prep_kernel<<<dim3(6, 12), 512, smemA>>>(X, W1, b1, Wb);
    pair_kernel<<<dim3(12, 12), 512, smemB>>>(X, W2, b2, bb, out);
}

// round 9
// speedup vs baseline: 1.7037x; 1.0012x over previous
#include <cuda_runtime.h>
#include <cuda_bf16.h>

#define NG   768
#define H    128
#define PAD  132   // smem row stride in floats; 16B-aligned; PAD%32==4 -> conflict-free col access

typedef unsigned long long u64;

// Scratch: columns [0:128)=Ai, [128:256)=Bjb (=Bj+b1), [256:384)=Q (=Wb·x_j rows)
__device__ float g_pre[NG * 384];

// ------------------------- packed f32x2 helpers ----------------------------
union F2U { u64 u; float2 f; };

__device__ __forceinline__ u64 pk2(float lo, float hi) {
    F2U t; t.f = make_float2(lo, hi); return t.u;
}
__device__ __forceinline__ float2 upk2(u64 v) {
    F2U t; t.u = v; return t.f;
}
__device__ __forceinline__ u64 addx2(u64 a, u64 b) {
    u64 r;
    asm("add.rn.f32x2 %0, %1, %2;" : "=l"(r) : "l"(a), "l"(b));
    return r;
}
__device__ __forceinline__ u64 fmax2(u64 a, u64 b, u64 c) {
    u64 r;
    asm("fma.rn.f32x2 %0, %1, %2, %3;" : "=l"(r) : "l"(a), "l"(b), "l"(c));
    return r;
}
__device__ __forceinline__ u64 relux2(u64 s) {
    F2U t; t.u = s;
    t.f.x = fmaxf(t.f.x, 0.f);   // FMNMX on alu pipe, overlaps fma pipe
    t.f.y = fmaxf(t.f.y, 0.f);
    return t.u;
}

// ---------------------------------------------------------------------------
// Kernel 1: per-gene projections as one 768x384x128 GEMM (packed f32x2).
// 32x64 output tile (144 blocks -> full chip), 512 threads, 2x2 micro-tile.
// Output column kk: kk<128 -> Ai, kk<256 -> Bjb (+b1), kk<384 -> Q.
// ---------------------------------------------------------------------------
__global__ __launch_bounds__(512) void prep_kernel(
    const float* __restrict__ X, const float* __restrict__ W1,
    const float* __restrict__ b1, const float* __restrict__ Wb)
{
    extern __shared__ float sm[];
    float* Xs = sm;              // 32 rows x PAD
    float* Ws = sm + 32 * PAD;   // 64 rows x PAD

    const int i0 = blockIdx.y * 32;
    const int c0 = blockIdx.x * 64;
    const int tid = threadIdx.x;

    for (int q = tid; q < 1024; q += 512) {
        int r = q >> 5, mq = q & 31;
        *(float4*)(Xs + r * PAD + mq * 4) =
            *(const float4*)(X + (i0 + r) * H + mq * 4);
    }
    for (int q = tid; q < 2048; q += 512) {
        int r = q >> 5, mq = q & 31;
        int kk = c0 + r;
        const float* rp;
        if (kk < 128)      rp = W1 + kk * 256;
        else if (kk < 256) rp = W1 + (kk - 128) * 256 + 128;
        else               rp = Wb + (kk - 256) * 128;
        *(float4*)(Ws + r * PAD + mq * 4) = *(const float4*)(rp + mq * 4);
    }
    __syncthreads();

    const int tx = tid & 31, ty = tid >> 5;
    const int rl = ty * 2;   // 2 output rows; cols {tx, tx+32}

    u64 acc[4];
#pragma unroll
    for (int p = 0; p < 4; p++) acc[p] = 0ull;

#pragma unroll 2
    for (int m0 = 0; m0 < 128; m0 += 4) {
        ulonglong2 xr[2], wc[2];
#pragma unroll
        for (int r = 0; r < 2; r++)
            xr[r] = *(const ulonglong2*)(Xs + (rl + r) * PAD + m0);
        wc[0] = *(const ulonglong2*)(Ws + tx * PAD + m0);
        wc[1] = *(const ulonglong2*)(Ws + (tx + 32) * PAD + m0);

#pragma unroll
        for (int h = 0; h < 2; h++)
#pragma unroll
            for (int r = 0; r < 2; r++) {
                const u64 xh = h ? xr[r].y : xr[r].x;
#pragma unroll
                for (int c = 0; c < 2; c++) {
                    const u64 wh = h ? wc[c].y : wc[c].x;
                    acc[r * 2 + c] = fmax2(xh, wh, acc[r * 2 + c]);
                }
            }
    }

#pragma unroll
    for (int r = 0; r < 2; r++)
#pragma unroll
        for (int c = 0; c < 2; c++) {
            const int kk = c0 + tx + c * 32;
            float2 s = upk2(acc[r * 2 + c]);
            float v = s.x + s.y;
            if (kk >= 128 && kk < 256) v += b1[kk - 128];
            g_pre[(i0 + rl + r) * 384 + kk] = v;
        }
}

// ---------------------------------------------------------------------------
// Kernel 2: fused pairwise MLP + argmax + bilinear sign-combine.
// 64x64 tile, 512 threads, 4x2 micro-tile (rows il..il+3, cols {tx, tx+32}),
// packed f32x2 along k, k-loop unrolled x2 for load/compute overlap.
// Logit diffs: u = l0-l1, w = l1-l2.
// ---------------------------------------------------------------------------
__global__ __launch_bounds__(512) void pair_kernel(
    const float* __restrict__ X, const float* __restrict__ W2,
    const float* __restrict__ b2, const float* __restrict__ bb,
    float* __restrict__ out)
{
    extern __shared__ float sm[];
    float* As  = sm;                 // Ai  rows (i-side)
    float* Xi  = sm + 64 * PAD;      // X   rows (i-side)
    float* Bs  = sm + 2 * 64 * PAD;  // Bjb rows (j-side)
    float* Qs  = sm + 3 * 64 * PAD;  // Q   rows (j-side)
    float* wus = sm + 4 * 64 * PAD;        // W2[0]-W2[1], 128 floats
    float* wvs = sm + 4 * 64 * PAD + PAD;  // W2[1]-W2[2], 128 floats

    const int i0 = blockIdx.y * 64;
    const int j0 = blockIdx.x * 64;
    const int tid = threadIdx.x;

    for (int q = tid; q < 2048; q += 512) {
        int r = q >> 5, mq = q & 31;
        *(float4*)(As + r * PAD + mq * 4) = *(const float4*)(g_pre + (i0 + r) * 384 + mq * 4);
        *(float4*)(Xi + r * PAD + mq * 4) = *(const float4*)(X + (i0 + r) * H + mq * 4);
        *(float4*)(Bs + r * PAD + mq * 4) = *(const float4*)(g_pre + (j0 + r) * 384 + 128 + mq * 4);
        *(float4*)(Qs + r * PAD + mq * 4) = *(const float4*)(g_pre + (j0 + r) * 384 + 256 + mq * 4);
    }
    if (tid < 128) {
        wus[tid] = W2[tid]       - W2[128 + tid];
        wvs[tid] = W2[128 + tid] - W2[256 + tid];
    }
    __syncthreads();

    const float u0  = b2[0] - b2[1];
    const float w0  = b2[1] - b2[2];
    const float bb0 = bb[0];

    const int tx = tid & 31, ty = tid >> 5;
    const int il = ty * 4;   // cols {tx, tx+32}: stride PAD per lane -> conflict-free

    u64 u[8], w[8], af[8];
#pragma unroll
    for (int p = 0; p < 8; p++) {
        u[p]  = pk2(u0, 0.f);
        w[p]  = pk2(w0, 0.f);
        af[p] = pk2(bb0, 0.f);
    }

#pragma unroll 2
    for (int k0 = 0; k0 < 128; k0 += 4) {
        ulonglong2 a2[4], x2[4], bv[2], qv[2];
#pragma unroll
        for (int r = 0; r < 4; r++) {
            a2[r] = *(const ulonglong2*)(As + (il + r) * PAD + k0);
            x2[r] = *(const ulonglong2*)(Xi + (il + r) * PAD + k0);
        }
        bv[0] = *(const ulonglong2*)(Bs + tx * PAD + k0);
        bv[1] = *(const ulonglong2*)(Bs + (tx + 32) * PAD + k0);
        qv[0] = *(const ulonglong2*)(Qs + tx * PAD + k0);
        qv[1] = *(const ulonglong2*)(Qs + (tx + 32) * PAD + k0);
        const ulonglong2 wu2 = *(const ulonglong2*)(wus + k0);
        const ulonglong2 wv2 = *(const ulonglong2*)(wvs + k0);

#pragma unroll
        for (int h = 0; h < 2; h++) {
            const u64 wuh = h ? wu2.y : wu2.x;
            const u64 wvh = h ? wv2.y : wv2.x;
#pragma unroll
            for (int r = 0; r < 4; r++) {
                const u64 ah = h ? a2[r].y : a2[r].x;
                const u64 xh = h ? x2[r].y : x2[r].x;
#pragma unroll
                for (int c = 0; c < 2; c++) {
                    const int p = r * 2 + c;
                    const u64 bh = h ? bv[c].y : bv[c].x;
                    const u64 qh = h ? qv[c].y : qv[c].x;
                    const u64 t = relux2(addx2(ah, bh));
                    u[p]  = fmax2(t, wuh, u[p]);
                    w[p]  = fmax2(t, wvh, w[p]);
                    af[p] = fmax2(xh, qh, af[p]);
                }
            }
        }
    }

#pragma unroll
    for (int r = 0; r < 4; r++) {
        const int i = i0 + il + r;
#pragma unroll
        for (int c = 0; c < 2; c++) {
            const int p = r * 2 + c;
            const int j = j0 + tx + c * 32;
            float2 s;
            s = upk2(u[p]);  const float us = s.x + s.y;
            s = upk2(w[p]);  const float ws = s.x + s.y;
            s = upk2(af[p]); const float as = s.x + s.y;
            // first-max argmax on differences:
            // is0: l0>=l1 (u>=0) && l0>=l2 (u+w>=0); is2: !is0 && l2>l1 (w<0)
            const bool is0 = (us >= 0.f) && (us + ws >= 0.f);
            const bool is2 = !is0 && (ws < 0.f);
            float v = is0 ? as : (is2 ? -as : 0.f);
            if (i == j) v = 0.f;
            out[i * NG + j] = v;
        }
    }
}

extern "C" void kernel_launch(void* const* d_in, const int* in_sizes, int n_in,
                              void* d_out, int out_size)
{
    const float* X  = (const float*)d_in[0];  // [768,128]
    const float* W1 = (const float*)d_in[1];  // [128,256]
    const float* b1 = (const float*)d_in[2];  // [128]
    const float* W2 = (const float*)d_in[3];  // [3,128]
    const float* b2 = (const float*)d_in[4];  // [3]
    const float* Wb = (const float*)d_in[5];  // [1,128,128]
    const float* bb = (const float*)d_in[6];  // [1]
    float* out = (float*)d_out;

    const int smemA = (32 + 64) * PAD * (int)sizeof(float);            // 50688 B
    const int smemB = (4 * 64 * PAD + 2 * PAD) * (int)sizeof(float);   // 136224 B
    cudaFuncSetAttribute(prep_kernel, cudaFuncAttributeMaxDynamicSharedMemorySize, smemA);
    cudaFuncSetAttribute(pair_kernel, cudaFuncAttributeMaxDynamicSharedMemorySize, smemB);

    prep_kernel<<<dim3(6, 24), 512, smemA>>>(X, W1, b1, Wb);
    pair_kernel<<<dim3(12, 12), 512, smemB>>>(X, W2, b2, bb, out);
}